// round 3
// baseline (speedup 1.0000x reference)
#include <cuda_runtime.h>

// ---------------- problem constants ----------------
#define BB   128
#define SS   256
#define LL   200
#define DD   768
#define PD   50
#define FF   (DD + PD)        // 818
#define RR   400
#define HH   150
#define NW   (BB * LL)        // 25600
#define POL  4
#define NTAG 5
#define N4   (4 * HH)         // 600
#define KBI  (HH + 1)         // 151
#define KTRI (LL * POL)       // 800
#define OUT_AP_OFF  0
#define OUT_OP_OFF  (NW * NTAG)            // 128000
#define OUT_TRI_OFF (2 * NW * NTAG)        // 256000

// ---------------- scratch (static device globals; no allocation) ----------------
__device__ float g_h[NW * FF];        // pooled + concat features  [25600, 818]
__device__ float g_reduc[NW * RR];    // reduc                     [25600, 400]
__device__ float g_rep[NW * N4];      // ap|op|ap2|op2 (relu'd)    [25600, 600]
__device__ float g_aff[NW * N4];      // biaffine left             [25600, 600]
__device__ float g_Wcat[N4 * RR];     // packed head weights       [600, 400]
__device__ float g_bcat[N4];          // packed head biases        [600]

// ---------------- pack 4 head weights/biases into one GEMM operand ----------------
__global__ void pack_kernel(const float* __restrict__ W_ap, const float* __restrict__ b_ap,
                            const float* __restrict__ W_op, const float* __restrict__ b_op,
                            const float* __restrict__ W_ap2, const float* __restrict__ b_ap2,
                            const float* __restrict__ W_op2, const float* __restrict__ b_op2) {
    int idx = blockIdx.x * blockDim.x + threadIdx.x;
    const int WTOT = N4 * RR;
    if (idx < WTOT) {
        int n = idx / RR, k = idx - n * RR;
        const float* src;
        int nn = n;
        if (n < HH)           { src = W_ap;  }
        else if (n < 2 * HH)  { src = W_op;  nn = n - HH; }
        else if (n < 3 * HH)  { src = W_ap2; nn = n - 2 * HH; }
        else                  { src = W_op2; nn = n - 3 * HH; }
        g_Wcat[idx] = src[nn * RR + k];
    } else if (idx < WTOT + N4) {
        int n = idx - WTOT;
        const float* src;
        int nn = n;
        if (n < HH)           { src = b_ap;  }
        else if (n < 2 * HH)  { src = b_op;  nn = n - HH; }
        else if (n < 3 * HH)  { src = b_ap2; nn = n - 2 * HH; }
        else                  { src = b_op2; nn = n - 3 * HH; }
        g_bcat[n] = src[nn];
    }
}

// ---------------- pool subwords (ragged mean) + concat pos embedding ----------------
__global__ void pool_kernel(const float* __restrict__ bert,
                            const int* __restrict__ positions,
                            const int* __restrict__ postag,
                            const float* __restrict__ embed) {
    int idx = blockIdx.x * blockDim.x + threadIdx.x;
    if (idx >= NW * FF) return;
    int w = idx / FF;
    int f = idx - w * FF;
    float v;
    if (f < PD) {
        v = embed[postag[w] * PD + f];
    } else {
        int d  = f - PD;
        int s0 = positions[2 * w];
        int s1 = positions[2 * w + 1];
        int b  = w / LL;
        const float* base = bert + ((long)b * SS) * DD + d;
        float s = 0.f;
        for (int t = s0; t <= s1; t++) s += base[(long)t * DD];
        v = s / (float)(s1 - s0 + 1);
    }
    g_h[idx] = v;
}

// ---------------- generic tiled SGEMM-NT: C[M,N] = A[M,K] * W[N,K]^T (+bias)(relu) ----
// 64x64 tile, BK=16, 256 threads, 4x4 per thread.
__global__ __launch_bounds__(256) void sgemm_nt(
    const float* __restrict__ A, int lda,
    const float* __restrict__ W, int ldb,
    float* __restrict__ C, int ldc,
    int M, int N, int K,
    const float* __restrict__ bias, int relu)
{
    __shared__ float As[16][64];
    __shared__ float Bs[16][64];
    const int tid = threadIdx.x;
    const int tx = tid & 15, ty = tid >> 4;
    const int rowBase = blockIdx.y * 64;
    const int colBase = blockIdx.x * 64;

    float acc[4][4] = {};

    for (int kt = 0; kt < K; kt += 16) {
        #pragma unroll
        for (int t = 0; t < 4; t++) {
            int i = tid + t * 256;
            int r = i >> 4, kk = i & 15;
            int gm = rowBase + r, gk = kt + kk;
            As[kk][r] = (gm < M && gk < K) ? A[(long)gm * lda + gk] : 0.f;
        }
        #pragma unroll
        for (int t = 0; t < 4; t++) {
            int i = tid + t * 256;
            int c = i >> 4, kk = i & 15;
            int gn = colBase + c, gk = kt + kk;
            Bs[kk][c] = (gn < N && gk < K) ? W[(long)gn * ldb + gk] : 0.f;
        }
        __syncthreads();
        #pragma unroll
        for (int kk = 0; kk < 16; kk++) {
            float a[4], b[4];
            #pragma unroll
            for (int i = 0; i < 4; i++) a[i] = As[kk][ty * 4 + i];
            #pragma unroll
            for (int j = 0; j < 4; j++) b[j] = Bs[kk][tx * 4 + j];
            #pragma unroll
            for (int i = 0; i < 4; i++)
                #pragma unroll
                for (int j = 0; j < 4; j++)
                    acc[i][j] += a[i] * b[j];
        }
        __syncthreads();
    }

    #pragma unroll
    for (int i = 0; i < 4; i++) {
        int gm = rowBase + ty * 4 + i;
        if (gm >= M) continue;
        #pragma unroll
        for (int j = 0; j < 4; j++) {
            int gn = colBase + tx * 4 + j;
            if (gn >= N) continue;
            float v = acc[i][j];
            if (bias) v += bias[gn];
            if (relu) v = fmaxf(v, 0.f);
            C[(long)gm * ldc + gn] = v;
        }
    }
}

// ---------------- affine GEMM: g_aff[w,n] = sum_k in1[w,k] * W_bi[n,k]
// in1[w,k] = g_rep[w*600 + 300 + k] for k<150, 1.0 at k==150 ----------------
__global__ __launch_bounds__(256) void sgemm_affine(const float* __restrict__ W_bi) {
    __shared__ float As[16][64];
    __shared__ float Bs[16][64];
    const int tid = threadIdx.x;
    const int tx = tid & 15, ty = tid >> 4;
    const int rowBase = blockIdx.y * 64;
    const int colBase = blockIdx.x * 64;

    float acc[4][4] = {};

    for (int kt = 0; kt < KBI; kt += 16) {
        #pragma unroll
        for (int t = 0; t < 4; t++) {
            int i = tid + t * 256;
            int r = i >> 4, kk = i & 15;
            int gm = rowBase + r, gk = kt + kk;
            float v = 0.f;
            if (gk < HH)       v = g_rep[(long)gm * N4 + 300 + gk];
            else if (gk == HH) v = 1.f;
            As[kk][r] = v;
        }
        #pragma unroll
        for (int t = 0; t < 4; t++) {
            int i = tid + t * 256;
            int c = i >> 4, kk = i & 15;
            int gn = colBase + c, gk = kt + kk;
            Bs[kk][c] = (gn < N4 && gk < KBI) ? W_bi[(long)gn * KBI + gk] : 0.f;
        }
        __syncthreads();
        #pragma unroll
        for (int kk = 0; kk < 16; kk++) {
            float a[4], b[4];
            #pragma unroll
            for (int i = 0; i < 4; i++) a[i] = As[kk][ty * 4 + i];
            #pragma unroll
            for (int j = 0; j < 4; j++) b[j] = Bs[kk][tx * 4 + j];
            #pragma unroll
            for (int i = 0; i < 4; i++)
                #pragma unroll
                for (int j = 0; j < 4; j++)
                    acc[i][j] += a[i] * b[j];
        }
        __syncthreads();
    }

    #pragma unroll
    for (int i = 0; i < 4; i++) {
        int gm = rowBase + ty * 4 + i;
        #pragma unroll
        for (int j = 0; j < 4; j++) {
            int gn = colBase + tx * 4 + j;
            if (gn < N4) g_aff[(long)gm * N4 + gn] = acc[i][j];
        }
    }
}

// ---------------- batched tri GEMM + transposed epilogue ----------------
// rows = m (op_node index, 200), cols = k = l1*4+p (800), K = 150.
// out[TRI_OFF + (b*L + m)*800 + k]
__global__ __launch_bounds__(256) void tri_kernel(float* __restrict__ out) {
    __shared__ float As[16][64];
    __shared__ float Bs[16][64];
    const int tid = threadIdx.x;
    const int tx = tid & 15, ty = tid >> 4;
    const int rowBase = blockIdx.y * 64;      // m
    const int colBase = blockIdx.x * 64;      // k = l1*4+p
    const int b = blockIdx.z;
    const long bL = (long)b * LL;

    float acc[4][4] = {};

    for (int kt = 0; kt < HH; kt += 16) {
        #pragma unroll
        for (int t = 0; t < 4; t++) {
            int i = tid + t * 256;
            int r = i >> 4, kk = i & 15;
            int gm = rowBase + r, gk = kt + kk;
            As[kk][r] = (gm < LL && gk < HH) ? g_rep[(bL + gm) * N4 + 450 + gk] : 0.f;
        }
        #pragma unroll
        for (int t = 0; t < 4; t++) {
            int i = tid + t * 256;
            int c = i >> 4, kk = i & 15;
            int gn = colBase + c, gk = kt + kk;
            float v = 0.f;
            if (gn < KTRI && gk < HH)
                v = g_aff[(bL + (gn >> 2)) * N4 + (gn & 3) * HH + gk];
            Bs[kk][c] = v;
        }
        __syncthreads();
        #pragma unroll
        for (int kk = 0; kk < 16; kk++) {
            float a[4], bb[4];
            #pragma unroll
            for (int i = 0; i < 4; i++) a[i] = As[kk][ty * 4 + i];
            #pragma unroll
            for (int j = 0; j < 4; j++) bb[j] = Bs[kk][tx * 4 + j];
            #pragma unroll
            for (int i = 0; i < 4; i++)
                #pragma unroll
                for (int j = 0; j < 4; j++)
                    acc[i][j] += a[i] * bb[j];
        }
        __syncthreads();
    }

    #pragma unroll
    for (int i = 0; i < 4; i++) {
        int gm = rowBase + ty * 4 + i;            // m
        if (gm >= LL) continue;
        #pragma unroll
        for (int j = 0; j < 4; j++) {
            int gn = colBase + tx * 4 + j;        // k
            if (gn >= KTRI) continue;
            out[OUT_TRI_OFF + (bL + gm) * KTRI + gn] = acc[i][j];
        }
    }
}

// ---------------- tag heads (tiny) ----------------
__global__ void tag_kernel(const float* __restrict__ W_aptag, const float* __restrict__ b_aptag,
                           const float* __restrict__ W_optag, const float* __restrict__ b_optag,
                           float* __restrict__ out) {
    int idx = blockIdx.x * blockDim.x + threadIdx.x;
    if (idx >= NW * 10) return;
    int w = idx / 10, t = idx - w * 10;
    const float* rep;
    const float* wv;
    float acc;
    int off;
    if (t < NTAG) {
        rep = g_rep + (long)w * N4;                // ap_rep
        wv  = W_aptag + t * HH;
        acc = b_aptag[t];
        off = OUT_AP_OFF + w * NTAG + t;
    } else {
        int tt = t - NTAG;
        rep = g_rep + (long)w * N4 + HH;           // op_rep
        wv  = W_optag + tt * HH;
        acc = b_optag[tt];
        off = OUT_OP_OFF + w * NTAG + tt;
    }
    #pragma unroll 5
    for (int k = 0; k < HH; k++) acc += rep[k] * wv[k];
    out[off] = acc;
}

// ---------------- launch ----------------
extern "C" void kernel_launch(void* const* d_in, const int* in_sizes, int n_in,
                              void* d_out, int out_size) {
    const float* bert      = (const float*)d_in[0];
    const int*   positions = (const int*)  d_in[1];
    const int*   postag    = (const int*)  d_in[2];
    const float* embed     = (const float*)d_in[3];
    const float* W_reduc   = (const float*)d_in[4];
    const float* b_reduc   = (const float*)d_in[5];
    const float* W_ap      = (const float*)d_in[6];
    const float* b_ap      = (const float*)d_in[7];
    const float* W_op      = (const float*)d_in[8];
    const float* b_op      = (const float*)d_in[9];
    const float* W_ap2     = (const float*)d_in[10];
    const float* b_ap2     = (const float*)d_in[11];
    const float* W_op2     = (const float*)d_in[12];
    const float* b_op2     = (const float*)d_in[13];
    const float* W_aptag   = (const float*)d_in[14];
    const float* b_aptag   = (const float*)d_in[15];
    const float* W_optag   = (const float*)d_in[16];
    const float* b_optag   = (const float*)d_in[17];
    const float* W_bi      = (const float*)d_in[18];
    float* out = (float*)d_out;

    void* p;
    cudaGetSymbolAddress(&p, g_h);     float* ph     = (float*)p;
    cudaGetSymbolAddress(&p, g_reduc); float* preduc = (float*)p;
    cudaGetSymbolAddress(&p, g_rep);   float* prep   = (float*)p;
    cudaGetSymbolAddress(&p, g_Wcat);  float* pWcat  = (float*)p;
    cudaGetSymbolAddress(&p, g_bcat);  float* pbcat  = (float*)p;

    // 1) pack head weights
    {
        int tot = N4 * RR + N4;
        pack_kernel<<<(tot + 255) / 256, 256>>>(W_ap, b_ap, W_op, b_op, W_ap2, b_ap2, W_op2, b_op2);
    }
    // 2) pool + concat
    {
        int tot = NW * FF;
        pool_kernel<<<(tot + 255) / 256, 256>>>(bert, positions, postag, embed);
    }
    // 3) reduc = h @ W_reduc^T + b_reduc        [25600,400], K=818
    {
        dim3 grid((RR + 63) / 64, NW / 64);
        sgemm_nt<<<grid, 256>>>(ph, FF, W_reduc, FF, preduc, RR, NW, RR, FF, b_reduc, 0);
    }
    // 4) rep = relu(reduc @ Wcat^T + bcat)      [25600,600], K=400
    {
        dim3 grid((N4 + 63) / 64, NW / 64);
        sgemm_nt<<<grid, 256>>>(preduc, RR, pWcat, RR, prep, N4, NW, N4, RR, pbcat, 1);
    }
    // 5) tag heads -> ap_out, op_out
    {
        int tot = NW * 10;
        tag_kernel<<<(tot + 255) / 256, 256>>>(W_aptag, b_aptag, W_optag, b_optag, out);
    }
    // 6) affine = [ap_node, 1] @ W_bi^T         [25600,600], K=151
    {
        dim3 grid((N4 + 63) / 64, NW / 64);
        sgemm_affine<<<grid, 256>>>(W_bi);
    }
    // 7) tri (batched) + transposed write to triplet_out
    {
        dim3 grid((KTRI + 63) / 64, (LL + 63) / 64, BB);
        tri_kernel<<<grid, 256>>>(out);
    }
}

// round 4
// speedup vs baseline: 3.1343x; 3.1343x over previous
#include <cuda_runtime.h>

// ---------------- problem constants ----------------
#define BB   128
#define SS   256
#define LL   200
#define DD   768
#define PD   50
#define FF   818             // D + 50
#define FP   832             // FF padded to mult of 16
#define RR   400
#define HH   150
#define NW   (BB * LL)       // 25600
#define POL  4
#define NTAG 5
#define N4   (4 * HH)        // 600
#define KBIP 160             // 151 padded (bias col at 150)
#define KTRI (LL * POL)      // 800
#define OUT_AP_OFF  0
#define OUT_OP_OFF  (NW * NTAG)
#define OUT_TRI_OFF (2 * NW * NTAG)

#define LDSA 132             // smem row stride for A tiles (128 + pad)
#define LDSB 68              // smem row stride for B tiles (64 + pad)

// ---------------- scratch (__device__ globals are zero-initialized) ----------------
__device__ float g_h[NW * FP];          // pooled features, K padded   [25600, 832]
__device__ float g_reduc[NW * RR];      // reduc                       [25600, 400]
__device__ float g_rep[NW * N4];        // ap|op|ap2|op2 (relu'd)      [25600, 600]
__device__ float g_in1[NW * KBIP];      // [ap_node, 1, 0...]          [25600, 160]
__device__ float g_opn[NW * KBIP];      // [op_node, 0...]             [25600, 160]
__device__ float g_aff[NW * 4 * KBIP];  // affine, [w][p][160]         [25600, 640]
__device__ float g_Wcat[N4 * RR];       // packed head weights         [600, 400]
__device__ float g_bcat[N4];            // packed head biases          [600]
__device__ float g_Wr[RR * FP];         // W_reduc K-padded            [400, 832]
__device__ float g_Wbi[N4 * KBIP];      // W_bi K-padded               [600, 160]

// ---------------- pack weights (pad K dims, concat 4 heads) ----------------
__global__ void pack_kernel(const float* __restrict__ W_ap, const float* __restrict__ b_ap,
                            const float* __restrict__ W_op, const float* __restrict__ b_op,
                            const float* __restrict__ W_ap2, const float* __restrict__ b_ap2,
                            const float* __restrict__ W_op2, const float* __restrict__ b_op2,
                            const float* __restrict__ W_reduc, const float* __restrict__ W_bi) {
    int idx = blockIdx.x * blockDim.x + threadIdx.x;
    const int T0 = N4 * RR;            // 240000
    const int T1 = T0 + N4;            // +600
    const int T2 = T1 + RR * FP;       // +332800
    const int T3 = T2 + N4 * KBIP;     // +96000
    if (idx < T0) {
        int n = idx / RR, k = idx - n * RR;
        const float* src; int nn = n;
        if (n < HH)          { src = W_ap;  }
        else if (n < 2 * HH) { src = W_op;  nn = n - HH; }
        else if (n < 3 * HH) { src = W_ap2; nn = n - 2 * HH; }
        else                 { src = W_op2; nn = n - 3 * HH; }
        g_Wcat[idx] = src[nn * RR + k];
    } else if (idx < T1) {
        int n = idx - T0;
        const float* src; int nn = n;
        if (n < HH)          { src = b_ap;  }
        else if (n < 2 * HH) { src = b_op;  nn = n - HH; }
        else if (n < 3 * HH) { src = b_ap2; nn = n - 2 * HH; }
        else                 { src = b_op2; nn = n - 3 * HH; }
        g_bcat[n] = src[nn];
    } else if (idx < T2) {
        int i = idx - T1;
        int n = i / FP, k = i - n * FP;
        g_Wr[i] = (k < FF) ? W_reduc[n * FF + k] : 0.f;
    } else if (idx < T3) {
        int i = idx - T2;
        int n = i / KBIP, k = i - n * KBIP;
        g_Wbi[i] = (k < HH + 1) ? W_bi[n * (HH + 1) + k] : 0.f;
    }
}

// set bias-1 column of in1 (pads stay zero from static init)
__global__ void init_kernel() {
    int w = blockIdx.x * blockDim.x + threadIdx.x;
    if (w < NW) g_in1[w * KBIP + HH] = 1.0f;
}

// ---------------- pool subwords (ragged mean) + concat pos embedding ----------------
__global__ void pool_kernel(const float* __restrict__ bert,
                            const int* __restrict__ positions,
                            const int* __restrict__ postag,
                            const float* __restrict__ embed) {
    int idx = blockIdx.x * blockDim.x + threadIdx.x;
    if (idx >= NW * FP) return;
    int w = idx / FP;
    int f = idx - w * FP;
    float v = 0.f;
    if (f < PD) {
        v = embed[postag[w] * PD + f];
    } else if (f < FF) {
        int d  = f - PD;
        int s0 = positions[2 * w];
        int s1 = positions[2 * w + 1];
        int b  = w / LL;
        const float* base = bert + ((long)b * SS) * DD + d;
        float s = 0.f;
        for (int t = s0; t <= s1; t++) s += base[(long)t * DD];
        v = s / (float)(s1 - s0 + 1);
    }
    g_h[idx] = v;
}

// ---------------- SGEMM-NT 128x64, BK=16, 256 thr, 8x4 microtile, dbl-buffered ----
// C[M,N] = A[M,K] * W[N,K]^T (+bias)(relu).  K % 16 == 0, lda/ldb % 4 == 0.
// OUTMODE: 0 plain, 1 also split-write ap_node->aux1 / op_node->aux2,
//          2 affine layout (C[w*640 + (n/150)*160 + n%150])
template<int RELU, int OUTMODE>
__global__ __launch_bounds__(256) void gemm_k(
    const float* __restrict__ A, int lda,
    const float* __restrict__ W, int ldb,
    float* __restrict__ C, int ldc,
    int M, int N, int K,
    const float* __restrict__ bias,
    float* __restrict__ aux1, float* __restrict__ aux2)
{
    __shared__ float As[2][16 * LDSA];
    __shared__ float Bs[2][16 * LDSB];
    const int tid = threadIdx.x;
    const int tx = tid & 15;           // N dim: 16 * 4
    const int ty = tid >> 4;           // M dim: 16 * 8
    const int rowBase = blockIdx.y * 128;
    const int colBase = blockIdx.x * 64;

    const int lm = tid >> 2;           // 0..63
    const int ak = (tid & 3) << 2;     // 0,4,8,12
    const int k4 = ak >> 2;

    const long arow0 = rowBase + lm;
    const long arow1 = rowBase + lm + 64;
    const long brow  = colBase + lm;
    const bool av0 = arow0 < M;
    const bool av1 = arow1 < M;
    const bool bv  = brow < N;

    const float4* Ap0 = (const float4*)(A + arow0 * lda);
    const float4* Ap1 = (const float4*)(A + arow1 * lda);
    const float4* Bp  = (const float4*)(W + brow * ldb);

    const float4 z4 = make_float4(0.f, 0.f, 0.f, 0.f);
    float4 ra0 = av0 ? Ap0[k4] : z4;
    float4 ra1 = av1 ? Ap1[k4] : z4;
    float4 rb  = bv  ? Bp[k4]  : z4;

    {
        float* as = As[0]; float* bs = Bs[0];
        as[(ak + 0) * LDSA + lm] = ra0.x;
        as[(ak + 1) * LDSA + lm] = ra0.y;
        as[(ak + 2) * LDSA + lm] = ra0.z;
        as[(ak + 3) * LDSA + lm] = ra0.w;
        as[(ak + 0) * LDSA + lm + 64] = ra1.x;
        as[(ak + 1) * LDSA + lm + 64] = ra1.y;
        as[(ak + 2) * LDSA + lm + 64] = ra1.z;
        as[(ak + 3) * LDSA + lm + 64] = ra1.w;
        bs[(ak + 0) * LDSB + lm] = rb.x;
        bs[(ak + 1) * LDSB + lm] = rb.y;
        bs[(ak + 2) * LDSB + lm] = rb.z;
        bs[(ak + 3) * LDSB + lm] = rb.w;
    }
    __syncthreads();

    float acc[8][4];
    #pragma unroll
    for (int i = 0; i < 8; i++)
        #pragma unroll
        for (int j = 0; j < 4; j++) acc[i][j] = 0.f;

    const int nt = K >> 4;
    for (int t = 0; t < nt; t++) {
        const int cur = t & 1;
        if (t + 1 < nt) {
            int idx = ((t + 1) << 2) + k4;
            ra0 = av0 ? Ap0[idx] : z4;
            ra1 = av1 ? Ap1[idx] : z4;
            rb  = bv  ? Bp[idx]  : z4;
        }
        const float* as = As[cur];
        const float* bs = Bs[cur];
        #pragma unroll
        for (int kk = 0; kk < 16; kk++) {
            float a[8], b[4];
            #pragma unroll
            for (int i = 0; i < 8; i++) a[i] = as[kk * LDSA + ty * 8 + i];
            #pragma unroll
            for (int j = 0; j < 4; j++) b[j] = bs[kk * LDSB + tx * 4 + j];
            #pragma unroll
            for (int i = 0; i < 8; i++)
                #pragma unroll
                for (int j = 0; j < 4; j++)
                    acc[i][j] = fmaf(a[i], b[j], acc[i][j]);
        }
        if (t + 1 < nt) {
            float* asn = As[cur ^ 1]; float* bsn = Bs[cur ^ 1];
            asn[(ak + 0) * LDSA + lm] = ra0.x;
            asn[(ak + 1) * LDSA + lm] = ra0.y;
            asn[(ak + 2) * LDSA + lm] = ra0.z;
            asn[(ak + 3) * LDSA + lm] = ra0.w;
            asn[(ak + 0) * LDSA + lm + 64] = ra1.x;
            asn[(ak + 1) * LDSA + lm + 64] = ra1.y;
            asn[(ak + 2) * LDSA + lm + 64] = ra1.z;
            asn[(ak + 3) * LDSA + lm + 64] = ra1.w;
            bsn[(ak + 0) * LDSB + lm] = rb.x;
            bsn[(ak + 1) * LDSB + lm] = rb.y;
            bsn[(ak + 2) * LDSB + lm] = rb.z;
            bsn[(ak + 3) * LDSB + lm] = rb.w;
        }
        __syncthreads();
    }

    #pragma unroll
    for (int i = 0; i < 8; i++) {
        int gm = rowBase + ty * 8 + i;
        if (gm >= M) continue;
        #pragma unroll
        for (int j = 0; j < 4; j++) {
            int gn = colBase + tx * 4 + j;
            if (gn >= N) continue;
            float v = acc[i][j];
            if (bias) v += bias[gn];
            if (RELU) v = fmaxf(v, 0.f);
            if (OUTMODE == 2) {
                int p = gn / HH, h = gn - p * HH;
                C[(long)gm * 4 * KBIP + p * KBIP + h] = v;
            } else {
                C[(long)gm * ldc + gn] = v;
                if (OUTMODE == 1) {
                    if (gn >= 300 && gn < 450)      aux1[(long)gm * KBIP + (gn - 300)] = v;
                    else if (gn >= 450)             aux2[(long)gm * KBIP + (gn - 450)] = v;
                }
            }
        }
    }
}

// ---------------- batched tri GEMM + transposed epilogue ----------------
// per batch b: rows m (200), cols gn = l1*4+p (800), K = 160 (padded; opn pads are 0)
__global__ __launch_bounds__(256) void tri_k(float* __restrict__ out) {
    __shared__ float As[2][16 * LDSA];
    __shared__ float Bs[2][16 * LDSB];
    const int tid = threadIdx.x;
    const int tx = tid & 15;
    const int ty = tid >> 4;
    const int rowBase = blockIdx.y * 128;
    const int colBase = blockIdx.x * 64;
    const int b = blockIdx.z;
    const long rb0 = (long)b * LL;

    const int lm = tid >> 2;
    const int ak = (tid & 3) << 2;
    const int k4 = ak >> 2;

    const int arow0 = rowBase + lm;
    const int arow1 = rowBase + lm + 64;
    const int gnb   = colBase + lm;
    const bool av0 = arow0 < LL;
    const bool av1 = arow1 < LL;
    const bool bv  = gnb < KTRI;

    const float4* Ap0 = (const float4*)(g_opn + (rb0 + arow0) * KBIP);
    const float4* Ap1 = (const float4*)(g_opn + (rb0 + arow1) * KBIP);
    const float4* Bp  = (const float4*)(g_aff + (rb0 + (gnb >> 2)) * 4 * KBIP + (gnb & 3) * KBIP);

    const float4 z4 = make_float4(0.f, 0.f, 0.f, 0.f);
    float4 ra0 = av0 ? Ap0[k4] : z4;
    float4 ra1 = av1 ? Ap1[k4] : z4;
    float4 rb  = bv  ? Bp[k4]  : z4;

    {
        float* as = As[0]; float* bs = Bs[0];
        as[(ak + 0) * LDSA + lm] = ra0.x;
        as[(ak + 1) * LDSA + lm] = ra0.y;
        as[(ak + 2) * LDSA + lm] = ra0.z;
        as[(ak + 3) * LDSA + lm] = ra0.w;
        as[(ak + 0) * LDSA + lm + 64] = ra1.x;
        as[(ak + 1) * LDSA + lm + 64] = ra1.y;
        as[(ak + 2) * LDSA + lm + 64] = ra1.z;
        as[(ak + 3) * LDSA + lm + 64] = ra1.w;
        bs[(ak + 0) * LDSB + lm] = rb.x;
        bs[(ak + 1) * LDSB + lm] = rb.y;
        bs[(ak + 2) * LDSB + lm] = rb.z;
        bs[(ak + 3) * LDSB + lm] = rb.w;
    }
    __syncthreads();

    float acc[8][4];
    #pragma unroll
    for (int i = 0; i < 8; i++)
        #pragma unroll
        for (int j = 0; j < 4; j++) acc[i][j] = 0.f;

    const int nt = KBIP >> 4;   // 10
    for (int t = 0; t < nt; t++) {
        const int cur = t & 1;
        if (t + 1 < nt) {
            int idx = ((t + 1) << 2) + k4;
            ra0 = av0 ? Ap0[idx] : z4;
            ra1 = av1 ? Ap1[idx] : z4;
            rb  = bv  ? Bp[idx]  : z4;
        }
        const float* as = As[cur];
        const float* bs = Bs[cur];
        #pragma unroll
        for (int kk = 0; kk < 16; kk++) {
            float a[8], bvv[4];
            #pragma unroll
            for (int i = 0; i < 8; i++) a[i] = as[kk * LDSA + ty * 8 + i];
            #pragma unroll
            for (int j = 0; j < 4; j++) bvv[j] = bs[kk * LDSB + tx * 4 + j];
            #pragma unroll
            for (int i = 0; i < 8; i++)
                #pragma unroll
                for (int j = 0; j < 4; j++)
                    acc[i][j] = fmaf(a[i], bvv[j], acc[i][j]);
        }
        if (t + 1 < nt) {
            float* asn = As[cur ^ 1]; float* bsn = Bs[cur ^ 1];
            asn[(ak + 0) * LDSA + lm] = ra0.x;
            asn[(ak + 1) * LDSA + lm] = ra0.y;
            asn[(ak + 2) * LDSA + lm] = ra0.z;
            asn[(ak + 3) * LDSA + lm] = ra0.w;
            asn[(ak + 0) * LDSA + lm + 64] = ra1.x;
            asn[(ak + 1) * LDSA + lm + 64] = ra1.y;
            asn[(ak + 2) * LDSA + lm + 64] = ra1.z;
            asn[(ak + 3) * LDSA + lm + 64] = ra1.w;
            bsn[(ak + 0) * LDSB + lm] = rb.x;
            bsn[(ak + 1) * LDSB + lm] = rb.y;
            bsn[(ak + 2) * LDSB + lm] = rb.z;
            bsn[(ak + 3) * LDSB + lm] = rb.w;
        }
        __syncthreads();
    }

    #pragma unroll
    for (int i = 0; i < 8; i++) {
        int gm = rowBase + ty * 8 + i;
        if (gm >= LL) continue;
        #pragma unroll
        for (int j = 0; j < 4; j++) {
            int gn = colBase + tx * 4 + j;
            if (gn >= KTRI) continue;
            out[(long)OUT_TRI_OFF + (rb0 + gm) * KTRI + gn] = acc[i][j];
        }
    }
}

// ---------------- tag heads (tiny) ----------------
__global__ void tag_kernel(const float* __restrict__ W_aptag, const float* __restrict__ b_aptag,
                           const float* __restrict__ W_optag, const float* __restrict__ b_optag,
                           float* __restrict__ out) {
    int idx = blockIdx.x * blockDim.x + threadIdx.x;
    if (idx >= NW * 10) return;
    int w = idx / 10, t = idx - w * 10;
    const float* rep;
    const float* wv;
    float acc;
    int off;
    if (t < NTAG) {
        rep = g_rep + (long)w * N4;
        wv  = W_aptag + t * HH;
        acc = b_aptag[t];
        off = OUT_AP_OFF + w * NTAG + t;
    } else {
        int tt = t - NTAG;
        rep = g_rep + (long)w * N4 + HH;
        wv  = W_optag + tt * HH;
        acc = b_optag[tt];
        off = OUT_OP_OFF + w * NTAG + tt;
    }
    #pragma unroll 5
    for (int k = 0; k < HH; k++) acc += rep[k] * wv[k];
    out[off] = acc;
}

// ---------------- launch ----------------
extern "C" void kernel_launch(void* const* d_in, const int* in_sizes, int n_in,
                              void* d_out, int out_size) {
    const float* bert      = (const float*)d_in[0];
    const int*   positions = (const int*)  d_in[1];
    const int*   postag    = (const int*)  d_in[2];
    const float* embed     = (const float*)d_in[3];
    const float* W_reduc   = (const float*)d_in[4];
    const float* b_reduc   = (const float*)d_in[5];
    const float* W_ap      = (const float*)d_in[6];
    const float* b_ap      = (const float*)d_in[7];
    const float* W_op      = (const float*)d_in[8];
    const float* b_op      = (const float*)d_in[9];
    const float* W_ap2     = (const float*)d_in[10];
    const float* b_ap2     = (const float*)d_in[11];
    const float* W_op2     = (const float*)d_in[12];
    const float* b_op2     = (const float*)d_in[13];
    const float* W_aptag   = (const float*)d_in[14];
    const float* b_aptag   = (const float*)d_in[15];
    const float* W_optag   = (const float*)d_in[16];
    const float* b_optag   = (const float*)d_in[17];
    const float* W_bi      = (const float*)d_in[18];
    float* out = (float*)d_out;

    void* p;
    cudaGetSymbolAddress(&p, g_h);     float* ph     = (float*)p;
    cudaGetSymbolAddress(&p, g_reduc); float* preduc = (float*)p;
    cudaGetSymbolAddress(&p, g_rep);   float* prep   = (float*)p;
    cudaGetSymbolAddress(&p, g_in1);   float* pin1   = (float*)p;
    cudaGetSymbolAddress(&p, g_opn);   float* popn   = (float*)p;
    cudaGetSymbolAddress(&p, g_aff);   float* paff   = (float*)p;
    cudaGetSymbolAddress(&p, g_Wcat);  float* pWcat  = (float*)p;
    cudaGetSymbolAddress(&p, g_bcat);  float* pbcat  = (float*)p;
    cudaGetSymbolAddress(&p, g_Wr);    float* pWr    = (float*)p;
    cudaGetSymbolAddress(&p, g_Wbi);   float* pWbi   = (float*)p;

    // 1) pack weights + init bias column
    {
        int tot = N4 * RR + N4 + RR * FP + N4 * KBIP;
        pack_kernel<<<(tot + 255) / 256, 256>>>(W_ap, b_ap, W_op, b_op, W_ap2, b_ap2,
                                                W_op2, b_op2, W_reduc, W_bi);
        init_kernel<<<(NW + 255) / 256, 256>>>();
    }
    // 2) pool + concat (padded)
    {
        int tot = NW * FP;
        pool_kernel<<<(tot + 255) / 256, 256>>>(bert, positions, postag, embed);
    }
    // 3) reduc = h @ Wr^T + b_reduc   [25600,400], K=832
    {
        dim3 grid((RR + 63) / 64, NW / 128);
        gemm_k<0, 0><<<grid, 256>>>(ph, FP, pWr, FP, preduc, RR, NW, RR, FP,
                                    b_reduc, nullptr, nullptr);
    }
    // 4) rep = relu(reduc @ Wcat^T + bcat)  [25600,600], K=400; also writes in1/opn
    {
        dim3 grid((N4 + 63) / 64, NW / 128);
        gemm_k<1, 1><<<grid, 256>>>(preduc, RR, pWcat, RR, prep, N4, NW, N4, RR,
                                    pbcat, pin1, popn);
    }
    // 5) tag heads
    {
        int tot = NW * 10;
        tag_kernel<<<(tot + 255) / 256, 256>>>(W_aptag, b_aptag, W_optag, b_optag, out);
    }
    // 6) affine = in1 @ Wbi^T  [25600,600], K=160 (bias folded into col 150)
    {
        dim3 grid((N4 + 63) / 64, NW / 128);
        gemm_k<0, 2><<<grid, 256>>>(pin1, KBIP, pWbi, KBIP, paff, 0, NW, N4, KBIP,
                                    nullptr, nullptr, nullptr);
    }
    // 7) tri (batched) + transposed write
    {
        dim3 grid((KTRI + 63) / 64, (LL + 127) / 128, BB);
        tri_k<<<grid, 256>>>(out);
    }
}

// round 5
// speedup vs baseline: 3.5532x; 1.1337x over previous
#include <cuda_runtime.h>

// ---------------- problem constants ----------------
#define BB   128
#define SS   256
#define LL   200
#define DD   768
#define PD   50
#define FF   818             // D + 50
#define FP   832             // FF padded to mult of 16
#define RR   400
#define HH   150
#define NW   (BB * LL)       // 25600
#define POL  4
#define NTAG 5
#define N4   (4 * HH)        // 600
#define KBIP 160             // 151 padded (bias col at 150)
#define KTRI (LL * POL)      // 800
#define OUT_AP_OFF  0
#define OUT_OP_OFF  (NW * NTAG)
#define OUT_TRI_OFF (2 * NW * NTAG)

#define LDSA 132             // smem row stride for A tiles (128 + pad)
#define LDSB 68              // smem row stride for B tiles (64 + pad)

// packed f32x2 FMA: d.lo += a.lo*b.lo ; d.hi += a.hi*b.hi  (Blackwell FFMA2)
#define FMA_F32X2(d, a, b) \
    asm("fma.rn.f32x2 %0, %1, %2, %0;" : "+l"(d) : "l"(a), "l"(b))
#define DUP_F32X2(d, s) \
    asm("mov.b64 %0, {%1, %1};" : "=l"(d) : "r"(__float_as_uint(s)))
#define UNPK_F32X2(lo, hi, s) \
    asm("mov.b64 {%0, %1}, %2;" : "=f"(lo), "=f"(hi) : "l"(s))

// ---------------- scratch (__device__ globals are zero-initialized) ----------------
__device__ float g_h[NW * FP];          // pooled features, K padded   [25600, 832]
__device__ float g_reduc[NW * RR];      // reduc                       [25600, 400]
__device__ float g_rep[NW * N4];        // ap|op|ap2|op2 (relu'd)      [25600, 600]
__device__ float g_in1[NW * KBIP];      // [ap_node, 1, 0...]          [25600, 160]
__device__ float g_opn[NW * KBIP];      // [op_node, 0...]             [25600, 160]
__device__ float g_aff[NW * 4 * KBIP];  // affine, [w][p][160]         [25600, 640]
__device__ float g_Wcat[N4 * RR];       // packed head weights         [600, 400]
__device__ float g_bcat[N4];            // packed head biases          [600]
__device__ float g_Wr[RR * FP];         // W_reduc K-padded            [400, 832]
__device__ float g_Wbi[N4 * KBIP];      // W_bi K-padded               [600, 160]

// ---------------- pack weights (pad K dims, concat 4 heads) ----------------
__global__ void pack_kernel(const float* __restrict__ W_ap, const float* __restrict__ b_ap,
                            const float* __restrict__ W_op, const float* __restrict__ b_op,
                            const float* __restrict__ W_ap2, const float* __restrict__ b_ap2,
                            const float* __restrict__ W_op2, const float* __restrict__ b_op2,
                            const float* __restrict__ W_reduc, const float* __restrict__ W_bi) {
    int idx = blockIdx.x * blockDim.x + threadIdx.x;
    const int T0 = N4 * RR;
    const int T1 = T0 + N4;
    const int T2 = T1 + RR * FP;
    const int T3 = T2 + N4 * KBIP;
    if (idx < T0) {
        int n = idx / RR, k = idx - n * RR;
        const float* src; int nn = n;
        if (n < HH)          { src = W_ap;  }
        else if (n < 2 * HH) { src = W_op;  nn = n - HH; }
        else if (n < 3 * HH) { src = W_ap2; nn = n - 2 * HH; }
        else                 { src = W_op2; nn = n - 3 * HH; }
        g_Wcat[idx] = src[nn * RR + k];
    } else if (idx < T1) {
        int n = idx - T0;
        const float* src; int nn = n;
        if (n < HH)          { src = b_ap;  }
        else if (n < 2 * HH) { src = b_op;  nn = n - HH; }
        else if (n < 3 * HH) { src = b_ap2; nn = n - 2 * HH; }
        else                 { src = b_op2; nn = n - 3 * HH; }
        g_bcat[n] = src[nn];
    } else if (idx < T2) {
        int i = idx - T1;
        int n = i / FP, k = i - n * FP;
        g_Wr[i] = (k < FF) ? W_reduc[n * FF + k] : 0.f;
    } else if (idx < T3) {
        int i = idx - T2;
        int n = i / KBIP, k = i - n * KBIP;
        g_Wbi[i] = (k < HH + 1) ? W_bi[n * (HH + 1) + k] : 0.f;
    }
}

// set bias-1 column of in1 (pads stay zero from static init)
__global__ void init_kernel() {
    int w = blockIdx.x * blockDim.x + threadIdx.x;
    if (w < NW) g_in1[w * KBIP + HH] = 1.0f;
}

// ---------------- pool subwords (ragged mean) + concat pos embedding ----------------
__global__ void pool_kernel(const float* __restrict__ bert,
                            const int* __restrict__ positions,
                            const int* __restrict__ postag,
                            const float* __restrict__ embed) {
    int idx = blockIdx.x * blockDim.x + threadIdx.x;
    if (idx >= NW * FP) return;
    int w = idx / FP;
    int f = idx - w * FP;
    float v = 0.f;
    if (f < PD) {
        v = embed[postag[w] * PD + f];
    } else if (f < FF) {
        int d  = f - PD;
        int s0 = positions[2 * w];
        int s1 = positions[2 * w + 1];
        int b  = w / LL;
        const float* base = bert + ((long)b * SS) * DD + d;
        float s = 0.f;
        for (int t = s0; t <= s1; t++) s += base[(long)t * DD];
        v = s / (float)(s1 - s0 + 1);
    }
    g_h[idx] = v;
}

// ---------------- SGEMM-NT 128x64, BK=16, 256 thr, 8x4 microtile, FFMA2 core ----
// C[M,N] = A[M,K] * W[N,K]^T (+bias)(relu).  K % 16 == 0, lda/ldb % 4 == 0.
// Row-pairs packed into f32x2: acc2[ip][j] holds rows (2ip, 2ip+1) x col j.
// OUTMODE: 0 plain, 1 also split-write ap_node->aux1 / op_node->aux2,
//          2 affine layout (C[w*640 + (n/150)*160 + n%150])
template<int RELU, int OUTMODE>
__global__ __launch_bounds__(256) void gemm_k(
    const float* __restrict__ A, int lda,
    const float* __restrict__ W, int ldb,
    float* __restrict__ C, int ldc,
    int M, int N, int K,
    const float* __restrict__ bias,
    float* __restrict__ aux1, float* __restrict__ aux2)
{
    __shared__ float As[2][16 * LDSA];
    __shared__ float Bs[2][16 * LDSB];
    const int tid = threadIdx.x;
    const int tx = tid & 15;           // N dim: 16 * 4
    const int ty = tid >> 4;           // M dim: 16 * 8
    const int rowBase = blockIdx.y * 128;
    const int colBase = blockIdx.x * 64;

    const int lm = tid >> 2;           // 0..63
    const int ak = (tid & 3) << 2;     // 0,4,8,12
    const int k4 = ak >> 2;

    const long arow0 = rowBase + lm;
    const long arow1 = rowBase + lm + 64;
    const long brow  = colBase + lm;
    const bool av0 = arow0 < M;
    const bool av1 = arow1 < M;
    const bool bv  = brow < N;

    const float4* Ap0 = (const float4*)(A + arow0 * lda);
    const float4* Ap1 = (const float4*)(A + arow1 * lda);
    const float4* Bp  = (const float4*)(W + brow * ldb);

    const float4 z4 = make_float4(0.f, 0.f, 0.f, 0.f);
    float4 ra0 = av0 ? Ap0[k4] : z4;
    float4 ra1 = av1 ? Ap1[k4] : z4;
    float4 rb  = bv  ? Bp[k4]  : z4;

    {
        float* as = As[0]; float* bs = Bs[0];
        as[(ak + 0) * LDSA + lm] = ra0.x;
        as[(ak + 1) * LDSA + lm] = ra0.y;
        as[(ak + 2) * LDSA + lm] = ra0.z;
        as[(ak + 3) * LDSA + lm] = ra0.w;
        as[(ak + 0) * LDSA + lm + 64] = ra1.x;
        as[(ak + 1) * LDSA + lm + 64] = ra1.y;
        as[(ak + 2) * LDSA + lm + 64] = ra1.z;
        as[(ak + 3) * LDSA + lm + 64] = ra1.w;
        bs[(ak + 0) * LDSB + lm] = rb.x;
        bs[(ak + 1) * LDSB + lm] = rb.y;
        bs[(ak + 2) * LDSB + lm] = rb.z;
        bs[(ak + 3) * LDSB + lm] = rb.w;
    }
    __syncthreads();

    unsigned long long acc2[4][4];
    #pragma unroll
    for (int i = 0; i < 4; i++)
        #pragma unroll
        for (int j = 0; j < 4; j++) acc2[i][j] = 0ull;

    const int nt = K >> 4;
    for (int t = 0; t < nt; t++) {
        const int cur = t & 1;
        if (t + 1 < nt) {
            int idx = ((t + 1) << 2) + k4;
            ra0 = av0 ? Ap0[idx] : z4;
            ra1 = av1 ? Ap1[idx] : z4;
            rb  = bv  ? Bp[idx]  : z4;
        }
        const float* as = As[cur];
        const float* bs = Bs[cur];
        #pragma unroll
        for (int kk = 0; kk < 16; kk++) {
            unsigned long long a2[4], bd[4];
            const float* arow = as + kk * LDSA + ty * 8;
            #pragma unroll
            for (int ip = 0; ip < 4; ip++)
                a2[ip] = *(const unsigned long long*)(arow + 2 * ip);
            float b0 = bs[kk * LDSB + tx * 4 + 0];
            float b1 = bs[kk * LDSB + tx * 4 + 1];
            float b2 = bs[kk * LDSB + tx * 4 + 2];
            float b3 = bs[kk * LDSB + tx * 4 + 3];
            DUP_F32X2(bd[0], b0);
            DUP_F32X2(bd[1], b1);
            DUP_F32X2(bd[2], b2);
            DUP_F32X2(bd[3], b3);
            #pragma unroll
            for (int ip = 0; ip < 4; ip++)
                #pragma unroll
                for (int j = 0; j < 4; j++)
                    FMA_F32X2(acc2[ip][j], a2[ip], bd[j]);
        }
        if (t + 1 < nt) {
            float* asn = As[cur ^ 1]; float* bsn = Bs[cur ^ 1];
            asn[(ak + 0) * LDSA + lm] = ra0.x;
            asn[(ak + 1) * LDSA + lm] = ra0.y;
            asn[(ak + 2) * LDSA + lm] = ra0.z;
            asn[(ak + 3) * LDSA + lm] = ra0.w;
            asn[(ak + 0) * LDSA + lm + 64] = ra1.x;
            asn[(ak + 1) * LDSA + lm + 64] = ra1.y;
            asn[(ak + 2) * LDSA + lm + 64] = ra1.z;
            asn[(ak + 3) * LDSA + lm + 64] = ra1.w;
            bsn[(ak + 0) * LDSB + lm] = rb.x;
            bsn[(ak + 1) * LDSB + lm] = rb.y;
            bsn[(ak + 2) * LDSB + lm] = rb.z;
            bsn[(ak + 3) * LDSB + lm] = rb.w;
        }
        __syncthreads();
    }

    #pragma unroll
    for (int ip = 0; ip < 4; ip++) {
        #pragma unroll
        for (int lane = 0; lane < 2; lane++) {
            int gm = rowBase + ty * 8 + 2 * ip + lane;
            if (gm >= M) continue;
            #pragma unroll
            for (int j = 0; j < 4; j++) {
                int gn = colBase + tx * 4 + j;
                if (gn >= N) continue;
                float lo, hi;
                UNPK_F32X2(lo, hi, acc2[ip][j]);
                float v = lane ? hi : lo;
                if (bias) v += bias[gn];
                if (RELU) v = fmaxf(v, 0.f);
                if (OUTMODE == 2) {
                    int p = gn / HH, h = gn - p * HH;
                    C[(long)gm * 4 * KBIP + p * KBIP + h] = v;
                } else {
                    C[(long)gm * ldc + gn] = v;
                    if (OUTMODE == 1) {
                        if (gn >= 300 && gn < 450)  aux1[(long)gm * KBIP + (gn - 300)] = v;
                        else if (gn >= 450)         aux2[(long)gm * KBIP + (gn - 450)] = v;
                    }
                }
            }
        }
    }
}

// ---------------- batched tri GEMM + transposed epilogue (FFMA2 core) ----------------
// per batch b: rows m (200), cols gn = l1*4+p (800), K = 160 (padded; opn pads are 0)
__global__ __launch_bounds__(256) void tri_k(float* __restrict__ out) {
    __shared__ float As[2][16 * LDSA];
    __shared__ float Bs[2][16 * LDSB];
    const int tid = threadIdx.x;
    const int tx = tid & 15;
    const int ty = tid >> 4;
    const int rowBase = blockIdx.y * 128;
    const int colBase = blockIdx.x * 64;
    const int b = blockIdx.z;
    const long rb0 = (long)b * LL;

    const int lm = tid >> 2;
    const int ak = (tid & 3) << 2;
    const int k4 = ak >> 2;

    const int arow0 = rowBase + lm;
    const int arow1 = rowBase + lm + 64;
    const int gnb   = colBase + lm;
    const bool av0 = arow0 < LL;
    const bool av1 = arow1 < LL;
    const bool bv  = gnb < KTRI;

    const float4* Ap0 = (const float4*)(g_opn + (rb0 + arow0) * KBIP);
    const float4* Ap1 = (const float4*)(g_opn + (rb0 + arow1) * KBIP);
    const float4* Bp  = (const float4*)(g_aff + (rb0 + (gnb >> 2)) * 4 * KBIP + (gnb & 3) * KBIP);

    const float4 z4 = make_float4(0.f, 0.f, 0.f, 0.f);
    float4 ra0 = av0 ? Ap0[k4] : z4;
    float4 ra1 = av1 ? Ap1[k4] : z4;
    float4 rb  = bv  ? Bp[k4]  : z4;

    {
        float* as = As[0]; float* bs = Bs[0];
        as[(ak + 0) * LDSA + lm] = ra0.x;
        as[(ak + 1) * LDSA + lm] = ra0.y;
        as[(ak + 2) * LDSA + lm] = ra0.z;
        as[(ak + 3) * LDSA + lm] = ra0.w;
        as[(ak + 0) * LDSA + lm + 64] = ra1.x;
        as[(ak + 1) * LDSA + lm + 64] = ra1.y;
        as[(ak + 2) * LDSA + lm + 64] = ra1.z;
        as[(ak + 3) * LDSA + lm + 64] = ra1.w;
        bs[(ak + 0) * LDSB + lm] = rb.x;
        bs[(ak + 1) * LDSB + lm] = rb.y;
        bs[(ak + 2) * LDSB + lm] = rb.z;
        bs[(ak + 3) * LDSB + lm] = rb.w;
    }
    __syncthreads();

    unsigned long long acc2[4][4];
    #pragma unroll
    for (int i = 0; i < 4; i++)
        #pragma unroll
        for (int j = 0; j < 4; j++) acc2[i][j] = 0ull;

    const int nt = KBIP >> 4;   // 10
    for (int t = 0; t < nt; t++) {
        const int cur = t & 1;
        if (t + 1 < nt) {
            int idx = ((t + 1) << 2) + k4;
            ra0 = av0 ? Ap0[idx] : z4;
            ra1 = av1 ? Ap1[idx] : z4;
            rb  = bv  ? Bp[idx]  : z4;
        }
        const float* as = As[cur];
        const float* bs = Bs[cur];
        #pragma unroll
        for (int kk = 0; kk < 16; kk++) {
            unsigned long long a2[4], bd[4];
            const float* arow = as + kk * LDSA + ty * 8;
            #pragma unroll
            for (int ip = 0; ip < 4; ip++)
                a2[ip] = *(const unsigned long long*)(arow + 2 * ip);
            float b0 = bs[kk * LDSB + tx * 4 + 0];
            float b1 = bs[kk * LDSB + tx * 4 + 1];
            float b2 = bs[kk * LDSB + tx * 4 + 2];
            float b3 = bs[kk * LDSB + tx * 4 + 3];
            DUP_F32X2(bd[0], b0);
            DUP_F32X2(bd[1], b1);
            DUP_F32X2(bd[2], b2);
            DUP_F32X2(bd[3], b3);
            #pragma unroll
            for (int ip = 0; ip < 4; ip++)
                #pragma unroll
                for (int j = 0; j < 4; j++)
                    FMA_F32X2(acc2[ip][j], a2[ip], bd[j]);
        }
        if (t + 1 < nt) {
            float* asn = As[cur ^ 1]; float* bsn = Bs[cur ^ 1];
            asn[(ak + 0) * LDSA + lm] = ra0.x;
            asn[(ak + 1) * LDSA + lm] = ra0.y;
            asn[(ak + 2) * LDSA + lm] = ra0.z;
            asn[(ak + 3) * LDSA + lm] = ra0.w;
            asn[(ak + 0) * LDSA + lm + 64] = ra1.x;
            asn[(ak + 1) * LDSA + lm + 64] = ra1.y;
            asn[(ak + 2) * LDSA + lm + 64] = ra1.z;
            asn[(ak + 3) * LDSA + lm + 64] = ra1.w;
            bsn[(ak + 0) * LDSB + lm] = rb.x;
            bsn[(ak + 1) * LDSB + lm] = rb.y;
            bsn[(ak + 2) * LDSB + lm] = rb.z;
            bsn[(ak + 3) * LDSB + lm] = rb.w;
        }
        __syncthreads();
    }

    #pragma unroll
    for (int ip = 0; ip < 4; ip++) {
        #pragma unroll
        for (int lane = 0; lane < 2; lane++) {
            int gm = rowBase + ty * 8 + 2 * ip + lane;
            if (gm >= LL) continue;
            #pragma unroll
            for (int j = 0; j < 4; j++) {
                int gn = colBase + tx * 4 + j;
                if (gn >= KTRI) continue;
                float lo, hi;
                UNPK_F32X2(lo, hi, acc2[ip][j]);
                out[(long)OUT_TRI_OFF + (rb0 + gm) * KTRI + gn] = lane ? hi : lo;
            }
        }
    }
}

// ---------------- tag heads (tiny) ----------------
__global__ void tag_kernel(const float* __restrict__ W_aptag, const float* __restrict__ b_aptag,
                           const float* __restrict__ W_optag, const float* __restrict__ b_optag,
                           float* __restrict__ out) {
    int idx = blockIdx.x * blockDim.x + threadIdx.x;
    if (idx >= NW * 10) return;
    int w = idx / 10, t = idx - w * 10;
    const float* rep;
    const float* wv;
    float acc;
    int off;
    if (t < NTAG) {
        rep = g_rep + (long)w * N4;
        wv  = W_aptag + t * HH;
        acc = b_aptag[t];
        off = OUT_AP_OFF + w * NTAG + t;
    } else {
        int tt = t - NTAG;
        rep = g_rep + (long)w * N4 + HH;
        wv  = W_optag + tt * HH;
        acc = b_optag[tt];
        off = OUT_OP_OFF + w * NTAG + tt;
    }
    #pragma unroll 5
    for (int k = 0; k < HH; k++) acc += rep[k] * wv[k];
    out[off] = acc;
}

// ---------------- launch ----------------
extern "C" void kernel_launch(void* const* d_in, const int* in_sizes, int n_in,
                              void* d_out, int out_size) {
    const float* bert      = (const float*)d_in[0];
    const int*   positions = (const int*)  d_in[1];
    const int*   postag    = (const int*)  d_in[2];
    const float* embed     = (const float*)d_in[3];
    const float* W_reduc   = (const float*)d_in[4];
    const float* b_reduc   = (const float*)d_in[5];
    const float* W_ap      = (const float*)d_in[6];
    const float* b_ap      = (const float*)d_in[7];
    const float* W_op      = (const float*)d_in[8];
    const float* b_op      = (const float*)d_in[9];
    const float* W_ap2     = (const float*)d_in[10];
    const float* b_ap2     = (const float*)d_in[11];
    const float* W_op2     = (const float*)d_in[12];
    const float* b_op2     = (const float*)d_in[13];
    const float* W_aptag   = (const float*)d_in[14];
    const float* b_aptag   = (const float*)d_in[15];
    const float* W_optag   = (const float*)d_in[16];
    const float* b_optag   = (const float*)d_in[17];
    const float* W_bi      = (const float*)d_in[18];
    float* out = (float*)d_out;

    void* p;
    cudaGetSymbolAddress(&p, g_h);     float* ph     = (float*)p;
    cudaGetSymbolAddress(&p, g_reduc); float* preduc = (float*)p;
    cudaGetSymbolAddress(&p, g_rep);   float* prep   = (float*)p;
    cudaGetSymbolAddress(&p, g_in1);   float* pin1   = (float*)p;
    cudaGetSymbolAddress(&p, g_opn);   float* popn   = (float*)p;
    cudaGetSymbolAddress(&p, g_aff);   float* paff   = (float*)p;
    cudaGetSymbolAddress(&p, g_Wcat);  float* pWcat  = (float*)p;
    cudaGetSymbolAddress(&p, g_bcat);  float* pbcat  = (float*)p;
    cudaGetSymbolAddress(&p, g_Wr);    float* pWr    = (float*)p;
    cudaGetSymbolAddress(&p, g_Wbi);   float* pWbi   = (float*)p;

    // 1) pack weights + init bias column
    {
        int tot = N4 * RR + N4 + RR * FP + N4 * KBIP;
        pack_kernel<<<(tot + 255) / 256, 256>>>(W_ap, b_ap, W_op, b_op, W_ap2, b_ap2,
                                                W_op2, b_op2, W_reduc, W_bi);
        init_kernel<<<(NW + 255) / 256, 256>>>();
    }
    // 2) pool + concat (padded)
    {
        int tot = NW * FP;
        pool_kernel<<<(tot + 255) / 256, 256>>>(bert, positions, postag, embed);
    }
    // 3) reduc = h @ Wr^T + b_reduc   [25600,400], K=832
    {
        dim3 grid((RR + 63) / 64, NW / 128);
        gemm_k<0, 0><<<grid, 256>>>(ph, FP, pWr, FP, preduc, RR, NW, RR, FP,
                                    b_reduc, nullptr, nullptr);
    }
    // 4) rep = relu(reduc @ Wcat^T + bcat)  [25600,600], K=400; also writes in1/opn
    {
        dim3 grid((N4 + 63) / 64, NW / 128);
        gemm_k<1, 1><<<grid, 256>>>(preduc, RR, pWcat, RR, prep, N4, NW, N4, RR,
                                    pbcat, pin1, popn);
    }
    // 5) tag heads
    {
        int tot = NW * 10;
        tag_kernel<<<(tot + 255) / 256, 256>>>(W_aptag, b_aptag, W_optag, b_optag, out);
    }
    // 6) affine = in1 @ Wbi^T  [25600,600], K=160 (bias folded into col 150)
    {
        dim3 grid((N4 + 63) / 64, NW / 128);
        gemm_k<0, 2><<<grid, 256>>>(pin1, KBIP, pWbi, KBIP, paff, 0, NW, N4, KBIP,
                                    nullptr, nullptr, nullptr);
    }
    // 7) tri (batched) + transposed write
    {
        dim3 grid((KTRI + 63) / 64, (LL + 127) / 128, BB);
        tri_k<<<grid, 256>>>(out);
    }
}